// round 7
// baseline (speedup 1.0000x reference)
#include <cuda_runtime.h>

#define B_TOT   4096
#define T_TOT   512
#define NF      16
#define NCHUNK  128     // chunks of 4 timesteps
#define XROW    20      // 16 floats + 4 pad

using u64 = unsigned long long;

#define PACK2(d, lo, hi)   asm("mov.b64 %0, {%1, %2};" : "=l"(d) : "f"(lo), "f"(hi))
#define UNPACK2(lo, hi, s) asm("mov.b64 {%0, %1}, %2;" : "=f"(lo), "=f"(hi) : "l"(s))
#define FMA2(d, a, b, c)   asm("fma.rn.f32x2 %0, %1, %2, %3;" : "=l"(d) : "l"(a), "l"(b), "l"(c))
#define ADD2(d, a, b)      asm("add.rn.f32x2 %0, %1, %2;" : "=l"(d) : "l"(a), "l"(b))
#define MUL2(d, a, b)      asm("mul.rn.f32x2 %0, %1, %2;" : "=l"(d) : "l"(a), "l"(b))

union Q4 { float4 f; u64 u[2]; };

__global__ void __launch_bounds__(256, 1)
gru_warp_kernel(const float* __restrict__ x,
                const float* __restrict__ w_ih,
                const float* __restrict__ w_hh,
                const float* __restrict__ b_ih,
                const float* __restrict__ b_hh,
                const float* __restrict__ fc_w,
                const float* __restrict__ fc_b,
                float* __restrict__ out)
{
    // per-warp double-buffered x tile: 16 rows (4 batches x 4 t) x XROW floats
    __shared__ __align__(16) float xs[8][2][16 * XROW];   // 20480 B

    const int tid   = threadIdx.x;
    const int wid   = tid >> 5;
    const int lane  = tid & 31;
    const int m     = lane & 3;
    const int cbp   = (lane >> 2) & 3;
    const int halfp = lane >> 4;
    const int batch0 = blockIdx.x * 32 + wid * 4;

    // ---- producer weights: gates {m, 4+m, 8+m}, packed over feature pairs ----
    u64 wp[3][8];
    u64 bq[3];
    #pragma unroll
    for (int q = 0; q < 3; ++q) {
        const int g = q * 4 + m;
        const float* wr = w_ih + g * NF;
        #pragma unroll
        for (int k = 0; k < 8; ++k) PACK2(wp[q][k], wr[2 * k], wr[2 * k + 1]);
        PACK2(bq[q], b_ih[g], 0.0f);
    }

    // ---- consumer weights: r/z packed, n scalar ----
    u64 whrz[4];                      // (w_r[m][k], w_z[m][k])
    float whn[4];
    #pragma unroll
    for (int k = 0; k < 4; ++k) {
        PACK2(whrz[k], w_hh[m * 4 + k], w_hh[(4 + m) * 4 + k]);
        whn[k] = w_hh[(8 + m) * 4 + k];
    }
    u64 bhrz; PACK2(bhrz, b_hh[m], b_hh[4 + m]);
    const float bhn = b_hh[8 + m];
    const float fw0 = fc_w[0], fw1 = fc_w[1], fw2 = fc_w[2], fw3 = fc_w[3];
    const float fb  = fc_b[0];

    // packed sigmoid constants
    u64 c05, cA, cB, cC;
    PACK2(c05, 0.5f, 0.5f);
    PACK2(cA, -0.05396825f, -0.05396825f);
    PACK2(cB,  0.13333333f,  0.13333333f);
    PACK2(cC, -0.33333333f, -0.33333333f);

    float h0 = 0.f, h1 = 0.f, h2 = 0.f, h3 = 0.f, hown = 0.f;
    const int src = lane & 12;   // quad base (lanes 16-31 mirror lower quads; values bounded, unused)

    // ---- warp-cooperative coalesced x load: 64 float4 per chunk, 2 per lane ----
    const int b_0 = lane >> 4,        b_1 = 2 + (lane >> 4);
    const int t_l = (lane >> 2) & 3,  f_l = lane & 3;
    const float* p0 = x + ((size_t)(batch0 + b_0) * T_TOT + t_l) * NF + f_l * 4;
    const float* p1 = x + ((size_t)(batch0 + b_1) * T_TOT + t_l) * NF + f_l * 4;
    const int soff0 = (b_0 * 4 + t_l) * XROW + f_l * 4;
    const int soff1 = (b_1 * 4 + t_l) * XROW + f_l * 4;

    float4 xn0, xn1;
    auto ldx = [&](int tc) {
        xn0 = *(const float4*)(p0 + (size_t)tc * 64);
        xn1 = *(const float4*)(p1 + (size_t)tc * 64);
    };
    auto stx = [&](int buf) {
        float* w = xs[wid][buf];
        *(float4*)(w + soff0) = xn0;
        *(float4*)(w + soff1) = xn1;
    };

    // ---- produce: this lane's t-half (2 timesteps) x 3 gate-dots ----
    auto produce = [&](int buf, float (&gl)[6]) {
        const float* base = xs[wid][buf] + (cbp * 4 + halfp * 2) * XROW;
        #pragma unroll
        for (int tt = 0; tt < 2; ++tt) {
            const float* r = base + tt * XROW;
            Q4 q0 = *(const Q4*)(r);
            Q4 q1 = *(const Q4*)(r + 4);
            Q4 q2 = *(const Q4*)(r + 8);
            Q4 q3 = *(const Q4*)(r + 12);
            #pragma unroll
            for (int q = 0; q < 3; ++q) {
                u64 acc = bq[q];
                FMA2(acc, q0.u[0], wp[q][0], acc);
                FMA2(acc, q0.u[1], wp[q][1], acc);
                FMA2(acc, q1.u[0], wp[q][2], acc);
                FMA2(acc, q1.u[1], wp[q][3], acc);
                FMA2(acc, q2.u[0], wp[q][4], acc);
                FMA2(acc, q2.u[1], wp[q][5], acc);
                FMA2(acc, q3.u[0], wp[q][6], acc);
                FMA2(acc, q3.u[1], wp[q][7], acc);
                float lo, hi; UNPACK2(lo, hi, acc);
                gl[tt * 3 + q] = lo + hi;
            }
        }
    };
    auto xchg = [&](const float (&gl)[6], float (&gu)[6]) {
        #pragma unroll
        for (int k = 0; k < 6; ++k)
            gu[k] = __shfl_sync(0xffffffffu, gl[k], lane | 16);
    };

    // ---- consume: 4 GRU steps, r/z fully packed in f32x2; ALL lanes run it ----
    auto consume = [&](const float (&gl)[6], const float (&gu)[6]) {
        u64 hh0, hh1, hh2, hh3;
        PACK2(hh0, h0, h0); PACK2(hh1, h1, h1);
        PACK2(hh2, h2, h2); PACK2(hh3, h3, h3);
        #pragma unroll
        for (int s = 0; s < 4; ++s) {
            const float gir = (s < 2) ? gl[s * 3 + 0] : gu[(s - 2) * 3 + 0];
            const float giz = (s < 2) ? gl[s * 3 + 1] : gu[(s - 2) * 3 + 1];
            const float gin = (s < 2) ? gl[s * 3 + 2] : gu[(s - 2) * 3 + 2];

            // packed (ar, az) = (gir,giz) + b + W_rz . h
            u64 arz, girz;
            PACK2(girz, gir, giz);
            ADD2(arz, girz, bhrz);
            FMA2(arz, hh0, whrz[0], arz);
            FMA2(arz, hh1, whrz[1], arz);
            FMA2(arz, hh2, whrz[2], arz);
            FMA2(arz, hh3, whrz[3], arz);

            float ghn = fmaf(whn[3], h3, fmaf(whn[2], h2,
                        fmaf(whn[1], h1, fmaf(whn[0], h0, bhn))));

            // packed sigmoid: 0.5 + 0.5*tanh(a/2), odd poly (|a/2|<=0.6)
            u64 y, u, p, yu, th, g;
            MUL2(y, arz, c05);
            MUL2(u, y, y);
            FMA2(p, u, cA, cB);
            FMA2(p, u, p, cC);
            MUL2(yu, y, u);
            FMA2(th, yu, p, y);
            FMA2(g, th, c05, c05);
            float rg, zg; UNPACK2(rg, zg, g);

            // n = tanh(gi_n + r*gh_n), Pade[5,4]
            float na   = fmaf(rg, ghn, gin);
            float un   = na * na;
            float nnum = fmaf(un, un + 105.f, 945.f);
            float nden = fmaf(un, fmaf(un, 15.f, 420.f), 945.f);
            float ng   = na * __fdividef(nnum, nden);

            float hm = fmaf(zg, hown - ng, ng);
            hown = hm;
            h0 = __shfl_sync(0xffffffffu, hm, src | 0);
            h1 = __shfl_sync(0xffffffffu, hm, src | 1);
            h2 = __shfl_sync(0xffffffffu, hm, src | 2);
            h3 = __shfl_sync(0xffffffffu, hm, src | 3);
            PACK2(hh0, h0, h0); PACK2(hh1, h1, h1);
            PACK2(hh2, h2, h2); PACK2(hh3, h3, h3);
        }
    };

    float glA[6], guA[6], glB[6], guB[6];

    // ---- prologue ----
    ldx(0);
    stx(0);
    __syncwarp();
    ldx(1);
    produce(0, glA);
    xchg(glA, guA);

    #pragma unroll 1
    for (int it = 0; it < NCHUNK; it += 2) {
        stx(1);
        __syncwarp();
        ldx(min(it + 2, NCHUNK - 1));
        produce(1, glB);
        xchg(glB, guB);
        consume(glA, guA);

        stx(0);
        __syncwarp();
        ldx(min(it + 3, NCHUNK - 1));
        produce(0, glA);
        xchg(glA, guA);
        consume(glB, guB);
    }

    if (lane < 16 && m == 0) {
        out[batch0 + cbp] = fmaf(h3, fw3, fmaf(h2, fw2,
                            fmaf(h1, fw1, fmaf(h0, fw0, fb))));
    }
}

extern "C" void kernel_launch(void* const* d_in, const int* in_sizes, int n_in,
                              void* d_out, int out_size)
{
    const float* x    = (const float*)d_in[0];
    const float* w_ih = (const float*)d_in[1];
    const float* w_hh = (const float*)d_in[2];
    const float* b_ih = (const float*)d_in[3];
    const float* b_hh = (const float*)d_in[4];
    const float* fc_w = (const float*)d_in[5];
    const float* fc_b = (const float*)d_in[6];
    float* out = (float*)d_out;

    gru_warp_kernel<<<B_TOT / 32, 256>>>(x, w_ih, w_hh, b_ih, b_hh, fc_w, fc_b, out);
}